// round 12
// baseline (speedup 1.0000x reference)
#include <cuda_runtime.h>
#include <cstdint>

// YOLO decode: persistent single-warp blocks, 3-deep cp.async pipeline,
// 32-box tiles, one lane per box, packed float4 streaming output stores.
// R11 base + CONTIGUOUS tile chunks per warp (one linear 260KB sweep/warp).
// Inputs: small [104,104,3,85] f32, middle [208,208,3,85] f32,
//         large [416,416,3,85] f32, pre_scale [6,3,2] f32.
// Output: [681408, 6] f32, rows zeroed where conf <= 0.5.

constexpr int N_SMALL  = 104 * 104 * 3;   // 32448  (mult of 32)
constexpr int N_MIDDLE = 208 * 208 * 3;   // 129792 (mult of 32)
constexpr int N_LARGE  = 416 * 416 * 3;   // 519168 (mult of 32)
constexpr int N_TOTAL  = N_SMALL + N_MIDDLE + N_LARGE;  // 681408
constexpr int TILE     = 32;
constexpr int N_TILES  = N_TOTAL / TILE;  // 21294
constexpr int NBLK     = 148 * 6;         // 888 single-warp blocks, 6/SM
constexpr int CHUNK    = (N_TILES + NBLK - 1) / NBLK;   // 24 tiles per warp
constexpr int V4T      = TILE * 85 / 4;   // 680 float4 per tile
constexpr int D        = 3;               // pipeline depth (buffers/warp)

static __device__ __forceinline__ void cp16(uint32_t dst_smem, const float4* src) {
    asm volatile("cp.async.cg.shared.global [%0], [%1], 16;\n"
                 :: "r"(dst_smem), "l"(src));
}
static __device__ __forceinline__ void cp_commit() {
    asm volatile("cp.async.commit_group;\n" ::: "memory");
}
template<int N>
static __device__ __forceinline__ void cp_wait() {
    asm volatile("cp.async.wait_group %0;\n" :: "n"(N) : "memory");
}

static __device__ __forceinline__ void tile_level(
    int t, const float* small, const float* middle, const float* large,
    const float*& in, int& lvl, int& r0)
{
    const int boxBase = t * TILE;
    if (boxBase < N_SMALL)                 { in = small;  lvl = 0; r0 = boxBase; }
    else if (boxBase < N_SMALL + N_MIDDLE) { in = middle; lvl = 1; r0 = boxBase - N_SMALL; }
    else                                   { in = large;  lvl = 2; r0 = boxBase - N_SMALL - N_MIDDLE; }
}

template<int S, int DECT>
static __device__ __forceinline__ void boxxform(
    int r, float tx, float ty, float tw, float th,
    const float* __restrict__ ps_sm,
    float& x, float& y, float& w, float& h)
{
    const int i = r / (3 * S);
    const int j = (r / 3) % S;
    const int a = r % 3;
    constexpr float invS = 1.0f / (float)S;
    x = (1.0f / (1.0f + __expf(-tx)) + (float)i) * invS;
    y = (1.0f / (1.0f + __expf(-ty)) + (float)j) * invS;
    const float aw = ps_sm[(DECT * 3 + a) * 2 + 0];
    const float ah = ps_sm[(DECT * 3 + a) * 2 + 1];
    w = __expf(tw) * aw * (1.0f / 416.0f);
    h = __expf(th) * ah * (1.0f / 416.0f);
}

__global__ __launch_bounds__(32) void HEAD_kernel(
    const float* __restrict__ small,
    const float* __restrict__ middle,
    const float* __restrict__ large,
    const float* __restrict__ pre_scale,
    float* __restrict__ out)
{
    __shared__ float4 sm[D][V4T];        // 32640 B
    __shared__ float  so[TILE * 6];      //   768 B output staging
    __shared__ float  sps[36];           // pre_scale cache [6,3,2]

    const int lane = threadIdx.x;

    if (lane < 32) sps[lane] = __ldg(pre_scale + lane);
    if (lane < 4)  sps[32 + lane] = __ldg(pre_scale + 32 + lane);
    __syncwarp();

    uint32_t sbase[D];
    #pragma unroll
    for (int k = 0; k < D; k++)
        sbase[k] = (uint32_t)__cvta_generic_to_shared(&sm[k][0]);

    // contiguous chunk: this warp owns tiles [t0, tEnd)
    const int t0   = blockIdx.x * CHUNK;
    const int tEnd = min(t0 + CHUNK, N_TILES);

    // stage one tile's copies into buffer `buf`; ALWAYS commits ONE group
    auto stage = [&](int t, int buf) {
        if (t < tEnd) {
            const float* in; int lvl, r0;
            tile_level(t, small, middle, large, in, lvl, r0);
            const float4* g4 = (const float4*)(in + (size_t)r0 * 85);
            const uint32_t sb = sbase[buf];
            #pragma unroll
            for (int j = 0; j < 22; j++) {
                const int idx = lane + 32 * j;
                if (idx < V4T) cp16(sb + idx * 16, g4 + idx);
            }
        }
        cp_commit();
    };

    auto compute = [&](int t, int buf) {
        const float* inu; int lvl, r0;
        tile_level(t, small, middle, large, inu, lvl, r0);

        const float* b = (const float*)&sm[buf][0] + lane * 85;
        const float conf = b[0];
        const float tx = b[1], ty = b[2], tw = b[3], th = b[4];

        // two-chain argmax over 80 logits, first-occurrence tie-break
        float b0 = b[5];  int i0 = 0;
        float b1 = b[6];  int i1 = 1;
        #pragma unroll
        for (int k = 2; k < 80; k += 2) {
            const float v0 = b[5 + k];
            const float v1 = b[6 + k];
            if (v0 > b0) { b0 = v0; i0 = k; }
            if (v1 > b1) { b1 = v1; i1 = k + 1; }
        }
        const int bi = (b1 > b0 || (b1 == b0 && i1 < i0)) ? i1 : i0;

        const int r = r0 + lane;
        float x, y, w, h;
        if (lvl == 0)      boxxform<104, 3>(r, tx, ty, tw, th, sps, x, y, w, h);
        else if (lvl == 1) boxxform<208, 4>(r, tx, ty, tw, th, sps, x, y, w, h);
        else               boxxform<416, 5>(r, tx, ty, tw, th, sps, x, y, w, h);

        const float mk = (conf > 0.5f) ? 1.0f : 0.0f;
        float* o = &so[lane * 6];
        o[0] = x * mk;
        o[1] = y * mk;
        o[2] = w * mk;
        o[3] = h * mk;
        o[4] = (float)bi * mk;
        o[5] = conf * mk;
        __syncwarp();
        // 32 boxes * 6 floats = 48 float4 -> two coalesced streaming rounds
        float4* og = (float4*)(out + (size_t)t * (TILE * 6));
        __stcs(og + lane, ((const float4*)so)[lane]);
        if (lane < 16) __stcs(og + 32 + lane, ((const float4*)so)[32 + lane]);
    };

    if (t0 >= N_TILES) return;           // warp-uniform (empty tail warps)

    #pragma unroll
    for (int k = 0; k < D - 1; k++) stage(t0 + k, k);

    int i = 0;
    for (int t = t0; t < tEnd; t++, i++) {
        cp_wait<D - 2>();                // tile t's group complete
        __syncwarp();                    // converge + prev-iter smem reuse
        compute(t, i % D);
        stage(t + (D - 1), (i + D - 1) % D);  // refill oldest buffer
    }
}

extern "C" void kernel_launch(void* const* d_in, const int* in_sizes, int n_in,
                              void* d_out, int out_size)
{
    const float* small     = (const float*)d_in[0];
    const float* middle    = (const float*)d_in[1];
    const float* large     = (const float*)d_in[2];
    const float* pre_scale = (const float*)d_in[3];
    float* out = (float*)d_out;

    HEAD_kernel<<<NBLK, 32>>>(small, middle, large, pre_scale, out);
}

// round 13
// speedup vs baseline: 1.0078x; 1.0078x over previous
#include <cuda_runtime.h>
#include <cstdint>

// YOLO decode — FINAL. Persistent single-warp blocks, 3-deep cp.async pipeline,
// 32-box tiles (interleaved across warps), one lane per box, smem-cached
// anchors, packed float4 streaming output stores. (= measured-best R11 with
// the stage-loop guard removed: 680 copies = 21 full rounds + 8-lane tail.)
// Inputs: small [104,104,3,85] f32, middle [208,208,3,85] f32,
//         large [416,416,3,85] f32, pre_scale [6,3,2] f32.
// Output: [681408, 6] f32, rows zeroed where conf <= 0.5.

constexpr int N_SMALL  = 104 * 104 * 3;   // 32448  (mult of 32)
constexpr int N_MIDDLE = 208 * 208 * 3;   // 129792 (mult of 32)
constexpr int N_LARGE  = 416 * 416 * 3;   // 519168 (mult of 32)
constexpr int N_TOTAL  = N_SMALL + N_MIDDLE + N_LARGE;  // 681408
constexpr int TILE     = 32;
constexpr int N_TILES  = N_TOTAL / TILE;  // 21294
constexpr int NBLK     = 148 * 6;         // 888 single-warp blocks, 6/SM
constexpr int TOTW     = NBLK;            // 888 warps, ~24 tiles each
constexpr int V4T      = TILE * 85 / 4;   // 680 float4 per tile = 21*32 + 8
constexpr int D        = 3;               // pipeline depth (buffers/warp)

static __device__ __forceinline__ void cp16(uint32_t dst_smem, const float4* src) {
    asm volatile("cp.async.cg.shared.global [%0], [%1], 16;\n"
                 :: "r"(dst_smem), "l"(src));
}
static __device__ __forceinline__ void cp_commit() {
    asm volatile("cp.async.commit_group;\n" ::: "memory");
}
template<int N>
static __device__ __forceinline__ void cp_wait() {
    asm volatile("cp.async.wait_group %0;\n" :: "n"(N) : "memory");
}

static __device__ __forceinline__ void tile_level(
    int t, const float* small, const float* middle, const float* large,
    const float*& in, int& lvl, int& r0)
{
    const int boxBase = t * TILE;
    if (boxBase < N_SMALL)                 { in = small;  lvl = 0; r0 = boxBase; }
    else if (boxBase < N_SMALL + N_MIDDLE) { in = middle; lvl = 1; r0 = boxBase - N_SMALL; }
    else                                   { in = large;  lvl = 2; r0 = boxBase - N_SMALL - N_MIDDLE; }
}

template<int S, int DECT>
static __device__ __forceinline__ void boxxform(
    int r, float tx, float ty, float tw, float th,
    const float* __restrict__ ps_sm,     // smem-cached [6,3,2] anchor table
    float& x, float& y, float& w, float& h)
{
    const int i = r / (3 * S);
    const int j = (r / 3) % S;
    const int a = r % 3;
    constexpr float invS = 1.0f / (float)S;
    x = (1.0f / (1.0f + __expf(-tx)) + (float)i) * invS;
    y = (1.0f / (1.0f + __expf(-ty)) + (float)j) * invS;
    const float aw = ps_sm[(DECT * 3 + a) * 2 + 0];
    const float ah = ps_sm[(DECT * 3 + a) * 2 + 1];
    w = __expf(tw) * aw * (1.0f / 416.0f);
    h = __expf(th) * ah * (1.0f / 416.0f);
}

__global__ __launch_bounds__(32) void HEAD_kernel(
    const float* __restrict__ small,
    const float* __restrict__ middle,
    const float* __restrict__ large,
    const float* __restrict__ pre_scale,
    float* __restrict__ out)
{
    __shared__ float4 sm[D][V4T];        // 32640 B
    __shared__ float  so[TILE * 6];      //   768 B output staging
    __shared__ float  sps[36];           // pre_scale cache [6,3,2]

    const int lane = threadIdx.x;
    const int gw   = blockIdx.x;

    // cache the anchor table once
    sps[lane] = __ldg(pre_scale + lane);
    if (lane < 4) sps[32 + lane] = __ldg(pre_scale + 32 + lane);
    __syncwarp();

    uint32_t sbase[D];
    #pragma unroll
    for (int k = 0; k < D; k++)
        sbase[k] = (uint32_t)__cvta_generic_to_shared(&sm[k][0]);

    // stage one tile's copies into buffer `buf`; ALWAYS commits ONE group
    auto stage = [&](int t, int buf) {
        if (t < N_TILES) {
            const float* in; int lvl, r0;
            tile_level(t, small, middle, large, in, lvl, r0);
            const float4* g4 = (const float4*)(in + (size_t)r0 * 85);
            const uint32_t sb = sbase[buf];
            #pragma unroll
            for (int j = 0; j < 21; j++) {           // 21 full rounds, no guard
                const int idx = lane + 32 * j;
                cp16(sb + idx * 16, g4 + idx);
            }
            if (lane < 8) {                          // tail: idx 672..679
                const int idx = 672 + lane;
                cp16(sb + idx * 16, g4 + idx);
            }
        }
        cp_commit();
    };

    auto compute = [&](int t, int buf) {
        const float* inu; int lvl, r0;
        tile_level(t, small, middle, large, inu, lvl, r0);

        const float* b = (const float*)&sm[buf][0] + lane * 85;
        const float conf = b[0];
        const float tx = b[1], ty = b[2], tw = b[3], th = b[4];

        // two-chain argmax over 80 logits, first-occurrence tie-break
        float b0 = b[5];  int i0 = 0;
        float b1 = b[6];  int i1 = 1;
        #pragma unroll
        for (int k = 2; k < 80; k += 2) {
            const float v0 = b[5 + k];
            const float v1 = b[6 + k];
            if (v0 > b0) { b0 = v0; i0 = k; }
            if (v1 > b1) { b1 = v1; i1 = k + 1; }
        }
        const int bi = (b1 > b0 || (b1 == b0 && i1 < i0)) ? i1 : i0;

        const int r = r0 + lane;
        float x, y, w, h;
        if (lvl == 0)      boxxform<104, 3>(r, tx, ty, tw, th, sps, x, y, w, h);
        else if (lvl == 1) boxxform<208, 4>(r, tx, ty, tw, th, sps, x, y, w, h);
        else               boxxform<416, 5>(r, tx, ty, tw, th, sps, x, y, w, h);

        const float mk = (conf > 0.5f) ? 1.0f : 0.0f;
        float* o = &so[lane * 6];
        o[0] = x * mk;
        o[1] = y * mk;
        o[2] = w * mk;
        o[3] = h * mk;
        o[4] = (float)bi * mk;
        o[5] = conf * mk;
        __syncwarp();
        // 32 boxes * 6 floats = 48 float4 -> two coalesced streaming rounds
        float4* og = (float4*)(out + (size_t)t * (TILE * 6));
        __stcs(og + lane, ((const float4*)so)[lane]);
        if (lane < 16) __stcs(og + 32 + lane, ((const float4*)so)[32 + lane]);
    };

    const int t0 = gw;

    #pragma unroll
    for (int k = 0; k < D - 1; k++) stage(t0 + k * TOTW, k);

    int i = 0;
    for (int t = t0; t < N_TILES; t += TOTW, i++) {
        cp_wait<D - 2>();                // tile t's group complete
        __syncwarp();                    // converge + prev-iter smem reuse
        compute(t, i % D);
        stage(t + (D - 1) * TOTW, (i + D - 1) % D);  // refill oldest buffer
    }
}

extern "C" void kernel_launch(void* const* d_in, const int* in_sizes, int n_in,
                              void* d_out, int out_size)
{
    const float* small     = (const float*)d_in[0];
    const float* middle    = (const float*)d_in[1];
    const float* large     = (const float*)d_in[2];
    const float* pre_scale = (const float*)d_in[3];
    float* out = (float*)d_out;

    HEAD_kernel<<<NBLK, 32>>>(small, middle, large, pre_scale, out);
}